// round 8
// baseline (speedup 1.0000x reference)
#include <cuda_runtime.h>
#include <stdint.h>

#define LL 401
#define BB 256
#define PLANE (LL * LL)          // 160801
#define BCH 64                   // batches per chunk
#define NCHUNK 4                 // BB / BCH
#define NQ 101                   // quads per row (covers 401 cols at any shift)
#define NT (LL * NQ)             // 40501 thread-slots per chunk
#define NBX ((NT + 255) / 256)   // 159
#define NBLK (NBX * NCHUNK)      // 636

// ---------------- device-global scratch (no allocations allowed) -------------
__device__ double g_bin[LL];             // per-distance-bin sum of cm
__device__ double g_W;                   // sum cm * same * maskf
__device__ double g_NC;                  // sum relu(cm) * non_conv
__device__ double g_bSame[BB];           // per-batch same*maskf count
__device__ double g_bNc[BB];             // per-batch non_conv count
__device__ unsigned char g_Pf[BB * LL];  // flat P: [b*401+pos] bit0=comp b1=any b2=f b3=r
__device__ unsigned int  g_Qu[4][25668]; // 4 shifted byte-copies of g_Pf, +4B front pad
__device__ unsigned int  g_done;         // last-block-done counter (self-resetting)

// ---------------- prep: pack bytes + shifted copies + per-batch counts -------
__global__ void k_prep(const float2* __restrict__ logits, const int* __restrict__ ctcf) {
    int b = blockIdx.x, t = threadIdx.x;
    if (b == 0) {                         // zero accumulators (graph is replayed)
        if (t < LL) g_bin[t] = 0.0;
        if (t == LL) { g_W = 0.0; g_NC = 0.0; }
    }
    __shared__ unsigned char sc[LL];
    __shared__ unsigned long long shw[16];
    unsigned long long pack = 0ull;
    if (t < LL) {
        int idx = b * LL + t;
        float2 l = logits[idx];
        int o = ctcf[idx];
        unsigned c = (l.y > l.x) ? 1u : 0u;      // argmax of 2 logits (tie -> 0)
        unsigned A = (o != 0) ? 1u : 0u;
        unsigned F = (o == 1) ? 1u : 0u;
        unsigned R = (o == -1) ? 1u : 0u;
        unsigned char byte = (unsigned char)(c | (A << 1) | (F << 2) | (R << 3));
        g_Pf[idx] = byte;
#pragma unroll
        for (int s = 0; s < 4; s++) {
            // Q_s[4 + idx - s] = Pf[idx]; offset 4+idx-s >= 1 always -> no guard.
            // (R7 bug: guarding on idx-s >= 0 left bytes for j < sigma unwritten.)
            ((unsigned char*)g_Qu[s])[4 + idx - s] = byte;
        }
        sc[t] = (unsigned char)c;
        pack = (unsigned long long)c
             | ((unsigned long long)F << 24)
             | ((unsigned long long)R << 36)
             | ((unsigned long long)A << 48);
    }
    __syncthreads();
    if (t < LL - 1) pack |= ((unsigned long long)(sc[t] == sc[t + 1] ? 1u : 0u)) << 12;

#pragma unroll
    for (int o = 16; o > 0; o >>= 1) pack += __shfl_down_sync(0xffffffffu, pack, o);
    if ((t & 31) == 0) shw[t >> 5] = pack;
    __syncthreads();
    if (t == 0) {
        unsigned long long s = 0;
        for (int w = 0; w < 16; w++) s += shw[w];
        double n1  = (double)(s & 0xFFFull);
        double adj = (double)((s >> 12) & 0xFFFull);
        double F   = (double)((s >> 24) & 0xFFFull);
        double R   = (double)((s >> 36) & 0xFFFull);
        double A   = (double)((s >> 48) & 0xFFFull);
        double n0  = (double)LL - n1;
        g_bSame[b] = n0 * n0 + n1 * n1 - (double)LL - 2.0 * adj;  // same & |i-j|>=2
        g_bNc[b]   = A * A - F * R;                               // non_conv count
    }
}

// ---------------- block reduction over 256 threads --------------------------
__device__ __forceinline__ double blockRed256(double v, double* sh) {
    int t = threadIdx.x;
#pragma unroll
    for (int o = 16; o > 0; o >>= 1) v += __shfl_down_sync(0xffffffffu, v, o);
    if ((t & 31) == 0) sh[t >> 5] = v;
    __syncthreads();
    double r;
    if (t < 32) {
        double w = (t < 8) ? sh[t] : 0.0;
#pragma unroll
        for (int o = 4; o > 0; o >>= 1) w += __shfl_down_sync(0xffffffffu, w, o);
        if (t == 0) sh[0] = w;
    }
    __syncthreads();
    r = sh[0];
    __syncthreads();
    return r;
}

// ---------------- main pass (float4 loads via per-plane shift) + finalize ----
__global__ void __launch_bounds__(256, 4) k_main(const float* __restrict__ cm,
                                                 float* __restrict__ out) {
    __shared__ double sbin[LL];
    int tid = threadIdx.x;
    int tq = blockIdx.x * 256 + tid;
    bool active = tq < NT;
    int tqc = active ? tq : 0;
    int i = tqc / NQ;                 // row 0..400
    int q = tqc - i * NQ;             // quad 0..100
    int b0 = blockIdx.y * BCH;        // chunk base batch (mult of 4)

    // ---- per-u static configs: s_u = (i+u)&3, window j in [4q-s, 4q-s+4) ----
    int j0[4];
    unsigned wSkip = 0, vMask = 0;
#pragma unroll
    for (int u = 0; u < 4; u++) {
        int s = (i + u) & 3;
        j0[u] = 4 * q - s;
#pragma unroll
        for (int k = 0; k < 4; k++) {
            int j = j0[u] + k;
            bool val = active && (j >= 0) && (j < LL);
            int d = (i > j) ? (i - j) : (j - i);
            bool w = val && (d >= 2);
            if (!w)  wSkip |= 1u << (4 * u + k);
            if (val) vMask |= 1u << (4 * u + k);
        }
    }

    // ---- pointers (all alignment-proven) ----
    int sigma = (4 - (i & 3)) & 3;    // Q-copy index = (-i) mod 4, per-thread const
    const unsigned char* qbase = (const unsigned char*)g_Qu[sigma];
    const float4* f4p[4];
    const unsigned char* qp[4];
#pragma unroll
    for (int u = 0; u < 4; u++) {
        long long A = (long long)(b0 + u) * PLANE + (long long)i * LL + j0[u];
        f4p[u] = reinterpret_cast<const float4*>(cm + A);       // A % 4 == 0
        int C = (b0 + u) * LL + j0[u];
        qp[u] = qbase + (4 + C - sigma);                        // word-aligned
    }
    int cio = b0 * LL + i;

    float4 a0 = {0,0,0,0}, a1 = {0,0,0,0}, a2 = {0,0,0,0}, a3 = {0,0,0,0};
    float accW = 0.f, accNC = 0.f;

#pragma unroll 2
    for (int g = 0; g < BCH / 4; g++) {
        float4 v0 = *f4p[0], v1 = *f4p[1], v2 = *f4p[2], v3 = *f4p[3];
        unsigned w0 = *(const unsigned*)qp[0];
        unsigned w1 = *(const unsigned*)qp[1];
        unsigned w2 = *(const unsigned*)qp[2];
        unsigned w3 = *(const unsigned*)qp[3];
        unsigned ci0 = g_Pf[cio];
        unsigned ci1 = g_Pf[cio + LL];
        unsigned ci2 = g_Pf[cio + 2 * LL];
        unsigned ci3 = g_Pf[cio + 3 * LL];
        f4p[0] += PLANE; f4p[1] += PLANE; f4p[2] += PLANE; f4p[3] += PLANE;
        qp[0] += 4 * LL; qp[1] += 4 * LL; qp[2] += 4 * LL; qp[3] += 4 * LL;
        cio += 4 * LL;

#define PR(acc, vv, cib, cjw, bit) {                                        \
        unsigned _cj = (cjw) >> (8 * ((bit) & 3));                          \
        (acc) += (vv);                                                      \
        if (((((cib) ^ _cj) | (wSkip >> (bit))) & 1u) == 0u) accW += (vv);  \
        unsigned _x = (cib) & _cj;                                          \
        unsigned _y = ((cib) << 1) & _cj;                                   \
        if ((_x & ~(_y >> 2) & ((vMask >> (bit) << 1) & 2u)) != 0u)         \
            accNC += fmaxf((vv), 0.f);                                      \
    }
        PR(a0.x, v0.x, ci0, w0, 0)  PR(a0.y, v0.y, ci0, w0, 1)
        PR(a0.z, v0.z, ci0, w0, 2)  PR(a0.w, v0.w, ci0, w0, 3)
        PR(a1.x, v1.x, ci1, w1, 4)  PR(a1.y, v1.y, ci1, w1, 5)
        PR(a1.z, v1.z, ci1, w1, 6)  PR(a1.w, v1.w, ci1, w1, 7)
        PR(a2.x, v2.x, ci2, w2, 8)  PR(a2.y, v2.y, ci2, w2, 9)
        PR(a2.z, v2.z, ci2, w2, 10) PR(a2.w, v2.w, ci2, w2, 11)
        PR(a3.x, v3.x, ci3, w3, 12) PR(a3.y, v3.y, ci3, w3, 13)
        PR(a3.z, v3.z, ci3, w3, 14) PR(a3.w, v3.w, ci3, w3, 15)
#undef PR
    }

    // ---- per-block bin aggregation in shared f64, then global f64 atomics ----
    sbin[tid] = 0.0;
    if (tid + 256 < LL) sbin[tid + 256] = 0.0;
    __syncthreads();
    if (active) {
#pragma unroll
        for (int u = 0; u < 4; u++) {
            float vals[4] = { u == 0 ? a0.x : u == 1 ? a1.x : u == 2 ? a2.x : a3.x,
                              u == 0 ? a0.y : u == 1 ? a1.y : u == 2 ? a2.y : a3.y,
                              u == 0 ? a0.z : u == 1 ? a1.z : u == 2 ? a2.z : a3.z,
                              u == 0 ? a0.w : u == 1 ? a1.w : u == 2 ? a2.w : a3.w };
#pragma unroll
            for (int k = 0; k < 4; k++) {
                if ((vMask >> (4 * u + k)) & 1u) {
                    int j = j0[u] + k;
                    int d = (i > j) ? (i - j) : (j - i);
                    atomicAdd(&sbin[d], (double)vals[k]);
                }
            }
        }
    }

    // ---- scalar reductions ----
#pragma unroll
    for (int o = 16; o > 0; o >>= 1) {
        accW  += __shfl_down_sync(0xffffffffu, accW,  o);
        accNC += __shfl_down_sync(0xffffffffu, accNC, o);
    }
    __shared__ double sW[8], sN[8];
    if ((tid & 31) == 0) { sW[tid >> 5] = accW; sN[tid >> 5] = accNC; }
    __syncthreads();
    if (tid == 0) {
        double w = 0.0, nn = 0.0;
#pragma unroll
        for (int z = 0; z < 8; z++) { w += sW[z]; nn += sN[z]; }
        atomicAdd(&g_W, w);
        atomicAdd(&g_NC, nn);
    }
    if (tid < LL)       atomicAdd(&g_bin[tid], sbin[tid]);
    if (tid + 256 < LL) atomicAdd(&g_bin[tid + 256], sbin[tid + 256]);

    // ---------- last-block-done: fused finalize ----------
    __shared__ bool isLast;
    __threadfence();
    if (tid == 0) {
        unsigned v0 = atomicAdd(&g_done, 1u);
        isLast = (v0 == (unsigned)(NBLK - 1));
    }
    __syncthreads();
    if (!isLast) return;
    if (tid == 0) g_done = 0;            // reset for next graph replay
    __threadfence();

    {
        __shared__ double sh[8];
        int t = tid;
        int t1 = t + 256;

        double bs0 = (t  < LL) ? g_bin[t]  : 0.0;
        double bs1 = (t1 < LL) ? g_bin[t1] : 0.0;
        double cnt0 = (t == 0) ? (double)LL : 2.0 * (double)(LL - t);
        double cnt1 = 2.0 * (double)(LL - t1);
        double mean0 = bs0 / (cnt0 * (double)BB);
        double mean1 = (t1 < LL) ? bs1 / (cnt1 * (double)BB) : 0.0;
        bool va0 = (t  < LL) && (t  >= 2) && isfinite(mean0) && (mean0 > 0.0);
        bool va1 = (t1 < LL)              && isfinite(mean1) && (mean1 > 0.0);
        double w0 = va0 ? 1.0 : 0.0, w1 = va1 ? 1.0 : 0.0;
        double ld0 = log(fmax((double)t, 1.0));
        double ld1 = log((double)t1);
        double lp0 = log((va0 ? mean0 : 1.0) + 1e-6);
        double lp1 = log((va1 ? mean1 : 1.0) + 1e-6);

        double n     = blockRed256(w0 + w1, sh);
        double sx    = blockRed256(w0 * ld0 + w1 * ld1, sh);
        double sy    = blockRed256(w0 * lp0 + w1 * lp1, sh);
        double tm    = blockRed256(((t >= 2 && t < LL) ? bs0 : 0.0) +
                                   ((t1 < LL) ? bs1 : 0.0), sh);
        double sameC = blockRed256(g_bSame[t], sh);     // exactly 256 batches
        double ncC   = blockRed256(g_bNc[t], sh);

        double nsafe = fmax(n, 1.0);
        double xm = sx / nsafe, ym = sy / nsafe;
        double num = blockRed256(w0 * (ld0 - xm) * (lp0 - ym) +
                                 w1 * (ld1 - xm) * (lp1 - ym), sh);
        double den = blockRed256(w0 * (ld0 - xm) * (ld0 - xm) +
                                 w1 * (ld1 - xm) * (ld1 - xm), sh) + 1e-8;

        if (t == 0) {
            double slope = num / den;
            double dist  = (n >= 5.0) ? (slope + 0.85) * (slope + 0.85) : 0.0;

            double ctcf = (ncC < 1.0) ? 0.0 : g_NC / (ncC + 1e-6);

            double diffC   = (double)BB * ((double)LL * LL - 3.0 * LL + 2.0) - sameC;
            double within  = g_W / fmax(sameC, 1.0);
            double between = (tm - g_W) / fmax(diffC, 1.0);
            double ratio   = within / (fabs(between) + 1e-6);
            double comp    = fmax(0.0, 1.5 - ratio);

            out[0] = (float)dist;
            out[1] = (float)ctcf;
            out[2] = (float)comp;
            out[3] = (float)(dist + 0.5 * ctcf + 0.5 * comp);
        }
    }
}

// ---------------- launch ----------------------------------------------------
extern "C" void kernel_launch(void* const* d_in, const int* in_sizes, int n_in,
                              void* d_out, int out_size) {
    const float* cm      = (const float*)d_in[0];
    const float2* logits = (const float2*)d_in[1];
    const int*   ctcf    = (const int*)d_in[2];
    float* out = (float*)d_out;

    k_prep<<<BB, 512>>>(logits, ctcf);
    k_main<<<dim3(NBX, NCHUNK), 256>>>(cm, out);
}